// round 3
// baseline (speedup 1.0000x reference)
#include <cuda_runtime.h>
#include <cuda_bf16.h>

#define T_LEN     16384
#define VEC_ROW   4096            // float4s per row
#define BLK       256
#define VPT       8               // float4 vecs per thread
#define NBLOCKS   1024            // (2^21 vecs) / (8 * 256)

__device__ float g_pnum[NBLOCKS];
__device__ float g_pden[NBLOCKS];
__device__ unsigned int g_ticket = 0;

__device__ __forceinline__ float warp_sum(float v) {
#pragma unroll
    for (int o = 16; o; o >>= 1) v += __shfl_xor_sync(0xffffffffu, v, o);
    return v;
}

// log(sigmoid(x)) = -log(1 + exp(-x)); eps term negligible for |x| < ~16
__device__ __forceinline__ float log_sig(float x) {
    return -__logf(1.0f + __expf(-x));   // LG2 + EX2 (2 MUFU, 2 FMUL)
}

__global__ void __launch_bounds__(BLK)
reinforce_fused(const float4* __restrict__ lp,
                const float4* __restrict__ lg,
                const float4* __restrict__ wt,
                float* __restrict__ out,
                int stride)   // total threads = nvec / VPT
{
    const int tid = blockIdx.x * BLK + threadIdx.x;
    float num = 0.0f, den = 0.0f;

#pragma unroll
    for (int half = 0; half < VPT / 4; ++half) {
        const int vb = tid + half * 4 * stride;
        // front-batch 12 independent LDG.128s -> high MLP
        float4 A0 = lp[vb];              float4 B0 = lg[vb];              float4 C0 = wt[vb];
        float4 A1 = lp[vb + stride];     float4 B1 = lg[vb + stride];     float4 C1 = wt[vb + stride];
        float4 A2 = lp[vb + 2 * stride]; float4 B2 = lg[vb + 2 * stride]; float4 C2 = wt[vb + 2 * stride];
        float4 A3 = lp[vb + 3 * stride]; float4 B3 = lg[vb + 3 * stride]; float4 C3 = wt[vb + 3 * stride];

#pragma unroll
        for (int k = 0; k < 4; ++k) {
            float4 a = (k == 0) ? A0 : (k == 1) ? A1 : (k == 2) ? A2 : A3;
            float4 b = (k == 0) ? B0 : (k == 1) ? B1 : (k == 2) ? B2 : B3;
            float4 c = (k == 0) ? C0 : (k == 1) ? C1 : (k == 2) ? C2 : C3;
            int v = vb + k * stride;
            float tb = (float)(((v & (VEC_ROW - 1)) << 2) + 1);

            num = fmaf(c.x * c.x * log_sig(b.x) * a.x, tb,        num);
            num = fmaf(c.y * c.y * log_sig(b.y) * a.y, tb + 1.0f, num);
            num = fmaf(c.z * c.z * log_sig(b.z) * a.z, tb + 2.0f, num);
            num = fmaf(c.w * c.w * log_sig(b.w) * a.w, tb + 3.0f, num);
            den += (c.x + c.y) + (c.z + c.w);
        }
    }

    // block reduction
    num = warp_sum(num);
    den = warp_sum(den);

    __shared__ float sn[BLK / 32], sd[BLK / 32];
    __shared__ unsigned int s_ticket;
    int wid = threadIdx.x >> 5, lid = threadIdx.x & 31;
    if (lid == 0) { sn[wid] = num; sd[wid] = den; }
    __syncthreads();
    if (threadIdx.x < BLK / 32) {
        num = sn[threadIdx.x];
        den = sd[threadIdx.x];
#pragma unroll
        for (int o = (BLK / 32) >> 1; o; o >>= 1) {
            num += __shfl_xor_sync(0xffu, num, o);
            den += __shfl_xor_sync(0xffu, den, o);
        }
        if (threadIdx.x == 0) {
            g_pnum[blockIdx.x] = num;
            g_pden[blockIdx.x] = den;
            __threadfence();
            s_ticket = atomicAdd(&g_ticket, 1u);
        }
    }
    __syncthreads();

    // last block reduces all partials in fixed order (deterministic)
    if (s_ticket == (unsigned)(gridDim.x - 1)) {
        float fn = 0.0f, fd = 0.0f;
        for (int i = threadIdx.x; i < NBLOCKS; i += BLK) {
            fn += g_pnum[i];
            fd += g_pden[i];
        }
        fn = warp_sum(fn);
        fd = warp_sum(fd);
        __syncthreads();
        if (lid == 0) { sn[wid] = fn; sd[wid] = fd; }
        __syncthreads();
        if (threadIdx.x < BLK / 32) {
            fn = sn[threadIdx.x];
            fd = sd[threadIdx.x];
#pragma unroll
            for (int o = (BLK / 32) >> 1; o; o >>= 1) {
                fn += __shfl_xor_sync(0xffu, fn, o);
                fd += __shfl_xor_sync(0xffu, fd, o);
            }
            if (threadIdx.x == 0) {
                out[0] = fn / fd;
                g_ticket = 0;          // reset for next graph replay
            }
        }
    }
}

extern "C" void kernel_launch(void* const* d_in, const int* in_sizes, int n_in,
                              void* d_out, int out_size)
{
    const float4* lp = (const float4*)d_in[0];  // log_probs [B,T]
    const float4* lg = (const float4*)d_in[1];  // logits    [B,T,1]
    const float4* wt = (const float4*)d_in[2];  // weight    [B,T]
    float* out = (float*)d_out;

    int n = in_sizes[0];            // 8388608
    int nvec = n >> 2;              // 2097152
    int threads_total = nvec / VPT; // 262144
    int grid = threads_total / BLK; // 1024 == NBLOCKS

    reinforce_fused<<<grid, BLK>>>(lp, lg, wt, out, threads_total);
}

// round 5
// speedup vs baseline: 1.1311x; 1.1311x over previous
#include <cuda_runtime.h>
#include <cuda_bf16.h>

#define VEC8_ROW 2048          // 8-float groups per T-row (T=16384)
#define BLK      256
#define NBLOCKS  1184          // 148 SMs * 8 CTAs

__device__ float g_pnum[NBLOCKS];
__device__ float g_pden[NBLOCKS];
__device__ unsigned int g_ticket = 0;

struct f8 { float v[8]; };

__device__ __forceinline__ float warp_sum(float x) {
#pragma unroll
    for (int o = 16; o; o >>= 1) x += __shfl_xor_sync(0xffffffffu, x, o);
    return x;
}

// log(sigmoid(x)) = -log(1 + exp(-x)); EPS term negligible at 1e-3 tolerance
__device__ __forceinline__ float log_sig(float x) {
    return -__logf(1.0f + __expf(-x));
}

// 256-bit load with L2 evict-last: the only form ptxas accepts the hint on
// for sm_103a, and it halves LDG count as a bonus.
__device__ __forceinline__ f8 ldg_el8(const float* p) {
    f8 r;
    asm("ld.global.nc.L2::evict_last.v8.b32 {%0,%1,%2,%3,%4,%5,%6,%7}, [%8];"
        : "=f"(r.v[0]), "=f"(r.v[1]), "=f"(r.v[2]), "=f"(r.v[3]),
          "=f"(r.v[4]), "=f"(r.v[5]), "=f"(r.v[6]), "=f"(r.v[7])
        : "l"(p));
    return r;
}

__global__ void __launch_bounds__(BLK)
reinforce_fused(const float* __restrict__ lp,
                const float* __restrict__ lg,
                const float* __restrict__ wt,
                float* __restrict__ out,
                int nvec8)
{
    float num = 0.0f, den = 0.0f;
    const int stride = gridDim.x * blockDim.x;
    for (int v = blockIdx.x * blockDim.x + threadIdx.x; v < nvec8; v += stride) {
        const int off = v << 3;
        f8 a = ldg_el8(lp + off);
        f8 b = ldg_el8(lg + off);
        f8 c = ldg_el8(wt + off);
        // t of element 0 in this group; row length 16384 % 8 == 0, no wrap
        float tb = (float)(((v & (VEC8_ROW - 1)) << 3) + 1);

#pragma unroll
        for (int k = 0; k < 8; ++k) {
            num = fmaf(c.v[k] * c.v[k] * log_sig(b.v[k]) * a.v[k],
                       tb + (float)k, num);
            den += c.v[k];
        }
    }

    // block reduction
    num = warp_sum(num);
    den = warp_sum(den);

    __shared__ float sn[BLK / 32], sd[BLK / 32];
    __shared__ unsigned int s_ticket;
    int wid = threadIdx.x >> 5, lid = threadIdx.x & 31;
    if (lid == 0) { sn[wid] = num; sd[wid] = den; }
    __syncthreads();
    if (threadIdx.x < BLK / 32) {
        num = sn[threadIdx.x];
        den = sd[threadIdx.x];
#pragma unroll
        for (int o = (BLK / 32) >> 1; o; o >>= 1) {
            num += __shfl_xor_sync(0xffu, num, o);
            den += __shfl_xor_sync(0xffu, den, o);
        }
        if (threadIdx.x == 0) {
            g_pnum[blockIdx.x] = num;
            g_pden[blockIdx.x] = den;
            __threadfence();
            s_ticket = atomicAdd(&g_ticket, 1u);
        }
    }
    __syncthreads();

    // last block reduces all partials in fixed order (deterministic)
    if (s_ticket == (unsigned)(gridDim.x - 1)) {
        float fn = 0.0f, fd = 0.0f;
        for (int i = threadIdx.x; i < NBLOCKS; i += BLK) {
            fn += g_pnum[i];
            fd += g_pden[i];
        }
        fn = warp_sum(fn);
        fd = warp_sum(fd);
        __syncthreads();
        if (lid == 0) { sn[wid] = fn; sd[wid] = fd; }
        __syncthreads();
        if (threadIdx.x < BLK / 32) {
            fn = sn[threadIdx.x];
            fd = sd[threadIdx.x];
#pragma unroll
            for (int o = (BLK / 32) >> 1; o; o >>= 1) {
                fn += __shfl_xor_sync(0xffu, fn, o);
                fd += __shfl_xor_sync(0xffu, fd, o);
            }
            if (threadIdx.x == 0) {
                out[0] = fn / fd;
                g_ticket = 0;          // reset for next graph replay
            }
        }
    }
}

extern "C" void kernel_launch(void* const* d_in, const int* in_sizes, int n_in,
                              void* d_out, int out_size)
{
    const float* lp = (const float*)d_in[0];  // log_probs [B,T]
    const float* lg = (const float*)d_in[1];  // logits    [B,T,1]
    const float* wt = (const float*)d_in[2];  // weight    [B,T]
    float* out = (float*)d_out;

    int n = in_sizes[0];     // 8388608
    int nvec8 = n >> 3;      // 1048576

    reinforce_fused<<<NBLOCKS, BLK>>>(lp, lg, wt, out, nvec8);
}